// round 1
// baseline (speedup 1.0000x reference)
#include <cuda_runtime.h>

#define NN 100000
#define EE 1000000
#define HH 64
#define GG 64
#define BN_EPS 1e-5f

// ---------------- scratch (static __device__, no allocations) ----------------
__device__ int    g_deg[NN];        // in-degree (excluding self loop)
__device__ int    g_off[NN];        // CSR offsets (exclusive scan of g_deg)
__device__ int    g_cur[NN];        // scatter cursors
__device__ int    g_csr[EE];        // CSR: source row per incoming edge, bucketed by dst
__device__ float  g_dinv[NN];       // rsqrt(deg+1)
__device__ float4 g_hs[NN * 16];    // transformed+scaled features
__device__ float4 g_buf[NN * 16];   // layer output buffer
__device__ float  g_pool[GG * 64];  // pooled sums
__device__ int    g_gstart[GG + 1]; // graph segment starts
__device__ int    g_bsum[64];       // scan block sums

// ---------------- init ----------------
__global__ void k_zero() {
    int i = blockIdx.x * blockDim.x + threadIdx.x;
    if (i < NN) { g_deg[i] = 0; g_cur[i] = 0; }
    if (i < GG * 64) g_pool[i] = 0.f;
}

// ---------------- degree histogram ----------------
__global__ void k_degree(const int* __restrict__ ei) {
    int e = blockIdx.x * blockDim.x + threadIdx.x;
    if (e >= EE) return;
    atomicAdd(&g_deg[ei[EE + e]], 1);   // col = edge_index[1]
}

__global__ void k_dinv() {
    int v = blockIdx.x * blockDim.x + threadIdx.x;
    if (v >= NN) return;
    g_dinv[v] = rsqrtf((float)(g_deg[v] + 1));  // +1 self loop; always > 0
}

// ---------------- exclusive scan of g_deg -> g_off (chunk = 2048/block) ----------------
__global__ void k_scan_a() {
    __shared__ int sh[256];
    int t = threadIdx.x;
    int base = blockIdx.x * 2048 + t * 8;
    int vals[8];
    int ts = 0;
#pragma unroll
    for (int j = 0; j < 8; j++) {
        int idx = base + j;
        vals[j] = (idx < NN) ? g_deg[idx] : 0;
        ts += vals[j];
    }
    sh[t] = ts;
    __syncthreads();
    // Hillis-Steele inclusive scan over 256 thread sums
#pragma unroll
    for (int d = 1; d < 256; d <<= 1) {
        int v = (t >= d) ? sh[t - d] : 0;
        __syncthreads();
        sh[t] += v;
        __syncthreads();
    }
    int excl = sh[t] - ts;
    int run = 0;
#pragma unroll
    for (int j = 0; j < 8; j++) {
        int idx = base + j;
        if (idx < NN) g_off[idx] = excl + run;
        run += vals[j];
    }
    if (t == 255) g_bsum[blockIdx.x] = sh[255];
}

__global__ void k_scan_b(int nblocks) {
    if (threadIdx.x == 0) {
        int run = 0;
        for (int b = 0; b < nblocks; b++) {
            int v = g_bsum[b];
            g_bsum[b] = run;
            run += v;
        }
    }
}

__global__ void k_scan_c() {
    int i = blockIdx.x * blockDim.x + threadIdx.x;
    if (i >= NN) return;
    g_off[i] += g_bsum[i >> 11];
}

// ---------------- CSR scatter ----------------
__global__ void k_scatter(const int* __restrict__ ei) {
    int e = blockIdx.x * blockDim.x + threadIdx.x;
    if (e >= EE) return;
    int r = ei[e];
    int c = ei[EE + e];
    int pos = g_off[c] + atomicAdd(&g_cur[c], 1);
    g_csr[pos] = r;
}

// ---------------- dense transform + row scale: out[v,:] = (X[v,:] @ W^T) * dinv[v] ----------------
__global__ void __launch_bounds__(256) k_gemm_scale(
    const float4* __restrict__ X4, const float* __restrict__ W, float4* __restrict__ O4) {
    __shared__ float4 sW[64 * 16];  // W[j][k] as float4 over k
    int t = threadIdx.x;
    const float4* W4 = (const float4*)W;
#pragma unroll
    for (int i = t; i < 1024; i += 256) sW[i] = W4[i];
    __syncthreads();
    int r = blockIdx.x * 256 + t;
    if (r >= NN) return;

    float acc[64];
#pragma unroll
    for (int j = 0; j < 64; j++) acc[j] = 0.f;

    const float4* xrow = X4 + r * 16;
    for (int kq = 0; kq < 16; kq++) {
        float4 xv = xrow[kq];
#pragma unroll
        for (int j = 0; j < 64; j++) {
            float4 w = sW[j * 16 + kq];  // warp-uniform -> broadcast LDS
            acc[j] = fmaf(xv.x, w.x, fmaf(xv.y, w.y, fmaf(xv.z, w.z, fmaf(xv.w, w.w, acc[j]))));
        }
    }
    float dv = g_dinv[r];
    float4* orow = O4 + r * 16;
#pragma unroll
    for (int jq = 0; jq < 16; jq++) {
        float4 o;
        o.x = acc[4 * jq + 0] * dv;
        o.y = acc[4 * jq + 1] * dv;
        o.z = acc[4 * jq + 2] * dv;
        o.w = acc[4 * jq + 3] * dv;
        orow[jq] = o;
    }
}

// ---------------- aggregation + bias + BN + ReLU (warp per node) ----------------
__global__ void k_agg(const float4* __restrict__ hs4, float* __restrict__ out,
                      const float* __restrict__ bias,
                      const float* __restrict__ bng, const float* __restrict__ bnb,
                      const float* __restrict__ bnm, const float* __restrict__ bnv) {
    int w = (blockIdx.x * blockDim.x + threadIdx.x) >> 5;
    if (w >= NN) return;
    int l = threadIdx.x & 31;
    const float2* base = (const float2*)hs4;  // 32 float2 per row

    float2 acc = base[w * 32 + l];  // self loop: hs[v]
    int s = g_off[w];
    int cnt = g_deg[w];
    int i = 0;
    for (; i + 4 <= cnt; i += 4) {
        int r0 = g_csr[s + i + 0];
        int r1 = g_csr[s + i + 1];
        int r2 = g_csr[s + i + 2];
        int r3 = g_csr[s + i + 3];
        float2 a0 = base[r0 * 32 + l];
        float2 a1 = base[r1 * 32 + l];
        float2 a2 = base[r2 * 32 + l];
        float2 a3 = base[r3 * 32 + l];
        acc.x += (a0.x + a1.x) + (a2.x + a3.x);
        acc.y += (a0.y + a1.y) + (a2.y + a3.y);
    }
    for (; i < cnt; i++) {
        int r = g_csr[s + i];
        float2 a = base[r * 32 + l];
        acc.x += a.x;
        acc.y += a.y;
    }
    float dv = g_dinv[w];
    int c = 2 * l;
    float px = fmaf(acc.x, dv, bias[c]);
    float py = fmaf(acc.y, dv, bias[c + 1]);
    float sx = bng[c] * rsqrtf(bnv[c] + BN_EPS);
    float sy = bng[c + 1] * rsqrtf(bnv[c + 1] + BN_EPS);
    float ox = fmaxf(0.f, fmaf(px - bnm[c], sx, bnb[c]));
    float oy = fmaxf(0.f, fmaf(py - bnm[c + 1], sy, bnb[c + 1]));
    ((float2*)out)[w * 32 + l] = make_float2(ox, oy);
}

// ---------------- graph boundaries from sorted batch ----------------
__global__ void k_bounds(const int* __restrict__ batch) {
    int v = blockIdx.x * blockDim.x + threadIdx.x;
    if (v > NN) return;
    int prev = (v == 0) ? -1 : batch[v - 1];
    int cur = (v < NN) ? batch[v] : GG;
    for (int g = prev + 1; g <= cur && g <= GG; g++) g_gstart[g] = v;
}

// ---------------- pooled sums (segments are contiguous) ----------------
__global__ void k_pool(const float* __restrict__ h) {
    __shared__ float sh[256];
    int g = blockIdx.x;
    int s = g_gstart[g];
    int e = g_gstart[g + 1];
    int t = threadIdx.x;
    int col = t & 63;
    float local = 0.f;
    for (int r = s + blockIdx.y * 4 + (t >> 6); r < e; r += 4 * gridDim.y)
        local += h[r * 64 + col];
    sh[t] = local;
    __syncthreads();
    if (t < 64) {
        float v = sh[t] + sh[t + 64] + sh[t + 128] + sh[t + 192];
        atomicAdd(&g_pool[g * 64 + t], v);
    }
}

// ---------------- MLP head ----------------
__global__ void k_head(const float* __restrict__ l1W, const float* __restrict__ l1b,
                       const float* __restrict__ l2W, const float* __restrict__ l2b,
                       float* __restrict__ out) {
    int g = threadIdx.x;
    if (g >= GG) return;
    int cnt = g_gstart[g + 1] - g_gstart[g];
    float inv = 1.f / fmaxf((float)cnt, 1.f);
    float p[64];
#pragma unroll
    for (int k = 0; k < 64; k++) p[k] = g_pool[g * 64 + k] * inv;
    float o = l2b[0];
    for (int j = 0; j < 32; j++) {
        float hsum = l1b[j];
#pragma unroll
        for (int k = 0; k < 64; k++) hsum = fmaf(p[k], l1W[j * 64 + k], hsum);
        o = fmaf(fmaxf(hsum, 0.f), l2W[j], o);
    }
    out[g] = o;
}

// ---------------- launch ----------------
extern "C" void kernel_launch(void* const* d_in, const int* in_sizes, int n_in,
                              void* d_out, int out_size) {
    const float* x      = (const float*)d_in[0];
    const int*   ei     = (const int*)d_in[1];
    const int*   batch  = (const int*)d_in[2];
    const float* W1     = (const float*)d_in[3];
    const float* b1     = (const float*)d_in[4];
    const float* W2     = (const float*)d_in[5];
    const float* b2     = (const float*)d_in[6];
    const float* bn1g   = (const float*)d_in[7];
    const float* bn1b   = (const float*)d_in[8];
    const float* bn1m   = (const float*)d_in[9];
    const float* bn1v   = (const float*)d_in[10];
    const float* bn2g   = (const float*)d_in[11];
    const float* bn2b   = (const float*)d_in[12];
    const float* bn2m   = (const float*)d_in[13];
    const float* bn2v   = (const float*)d_in[14];
    const float* l1W    = (const float*)d_in[15];
    const float* l1b    = (const float*)d_in[16];
    const float* l2W    = (const float*)d_in[17];
    const float* l2b    = (const float*)d_in[18];
    float* out = (float*)d_out;

    float4 *hs4, *buf4;
    cudaGetSymbolAddress((void**)&hs4, g_hs);
    cudaGetSymbolAddress((void**)&buf4, g_buf);

    const int TB = 256;
    int nb_n = (NN + TB - 1) / TB;
    int nb_e = (EE + TB - 1) / TB;
    int nb_scan = (NN + 2047) / 2048;  // 49

    k_zero<<<nb_n, TB>>>();
    k_degree<<<nb_e, TB>>>(ei);
    k_dinv<<<nb_n, TB>>>();
    k_scan_a<<<nb_scan, 256>>>();
    k_scan_b<<<1, 32>>>(nb_scan);
    k_scan_c<<<nb_n, TB>>>();
    k_scatter<<<nb_e, TB>>>(ei);

    // layer 1
    k_gemm_scale<<<nb_n, 256>>>((const float4*)x, W1, hs4);
    k_agg<<<(NN * 32 + TB - 1) / TB, TB>>>(hs4, (float*)buf4, b1, bn1g, bn1b, bn1m, bn1v);
    // layer 2
    k_gemm_scale<<<nb_n, 256>>>((const float4*)buf4, W2, hs4);
    k_agg<<<(NN * 32 + TB - 1) / TB, TB>>>(hs4, (float*)buf4, b2, bn2g, bn2b, bn2m, bn2v);

    // pooling + head
    k_bounds<<<(NN + 1 + TB - 1) / TB, TB>>>(batch);
    k_pool<<<dim3(GG, 8), 256>>>((const float*)buf4);
    k_head<<<1, 64>>>(l1W, l1b, l2W, l2b, out);
}

// round 2
// speedup vs baseline: 1.1812x; 1.1812x over previous
#include <cuda_runtime.h>

#define NN 100000
#define EE 1000000
#define HH 64
#define GG 64
#define BN_EPS 1e-5f

// ---------------- scratch (static __device__, no allocations) ----------------
__device__ int    g_deg[NN];        // in-degree (excluding self loop)
__device__ int    g_off[NN];        // CSR offsets (exclusive scan of g_deg)
__device__ int    g_cur[NN];        // scatter cursors
__device__ int    g_csr[EE];        // CSR: source row per incoming edge, bucketed by dst
__device__ float  g_dinv[NN];       // rsqrt(deg+1)
__device__ float4 g_hs[NN * 16];    // transformed+scaled features
__device__ float4 g_buf[NN * 16];   // layer output buffer
__device__ float  g_pool[GG * 64];  // pooled sums
__device__ int    g_gstart[GG + 1]; // graph segment starts
__device__ int    g_bsum[64];       // scan block sums

// ---------------- init: zero counters + pool, and graph bounds from sorted batch ----------------
__global__ void k_zero(const int* __restrict__ batch) {
    int i = blockIdx.x * blockDim.x + threadIdx.x;
    if (i < NN) { g_deg[i] = 0; g_cur[i] = 0; }
    if (i < GG * 64) g_pool[i] = 0.f;
    if (i <= NN) {
        int prev = (i == 0) ? -1 : batch[i - 1];
        int cur  = (i < NN) ? batch[i] : GG;
        for (int g = prev + 1; g <= cur && g <= GG; g++) g_gstart[g] = i;
    }
}

// ---------------- degree histogram ----------------
__global__ void k_degree(const int* __restrict__ ei) {
    int e = blockIdx.x * blockDim.x + threadIdx.x;
    if (e >= EE) return;
    atomicAdd(&g_deg[ei[EE + e]], 1);   // col = edge_index[1]
}

// ---------------- exclusive scan of g_deg -> g_off (chunk = 2048/block), fused dinv ----------------
__global__ void k_scan_a() {
    __shared__ int sh[256];
    int t = threadIdx.x;
    int base = blockIdx.x * 2048 + t * 8;
    int vals[8];
    int ts = 0;
#pragma unroll
    for (int j = 0; j < 8; j++) {
        int idx = base + j;
        vals[j] = (idx < NN) ? g_deg[idx] : 0;
        if (idx < NN) g_dinv[idx] = rsqrtf((float)(vals[j] + 1));  // +1 self loop
        ts += vals[j];
    }
    sh[t] = ts;
    __syncthreads();
#pragma unroll
    for (int d = 1; d < 256; d <<= 1) {
        int v = (t >= d) ? sh[t - d] : 0;
        __syncthreads();
        sh[t] += v;
        __syncthreads();
    }
    int excl = sh[t] - ts;
    int run = 0;
#pragma unroll
    for (int j = 0; j < 8; j++) {
        int idx = base + j;
        if (idx < NN) g_off[idx] = excl + run;
        run += vals[j];
    }
    if (t == 255) g_bsum[blockIdx.x] = sh[255];
}

// parallel exclusive scan of up to 64 block sums (one block, 64 threads)
__global__ void k_scan_b(int nblocks) {
    __shared__ int wsum[2];
    int t = threadIdx.x;
    int lane = t & 31, wid = t >> 5;
    int v = (t < nblocks) ? g_bsum[t] : 0;
    int s = v;
#pragma unroll
    for (int d = 1; d < 32; d <<= 1) {
        int u = __shfl_up_sync(0xFFFFFFFFu, s, d);
        if (lane >= d) s += u;
    }
    if (lane == 31) wsum[wid] = s;
    __syncthreads();
    int add = (wid == 1) ? wsum[0] : 0;
    if (t < nblocks) g_bsum[t] = s - v + add;  // exclusive
}

__global__ void k_scan_c() {
    int i = blockIdx.x * blockDim.x + threadIdx.x;
    if (i >= NN) return;
    g_off[i] += g_bsum[i >> 11];
}

// ---------------- CSR scatter ----------------
__global__ void k_scatter(const int* __restrict__ ei) {
    int e = blockIdx.x * blockDim.x + threadIdx.x;
    if (e >= EE) return;
    int r = ei[e];
    int c = ei[EE + e];
    int pos = g_off[c] + atomicAdd(&g_cur[c], 1);
    g_csr[pos] = r;
}

// ---------------- dense transform + row scale, packed f32x2 FMA ----------------
// out[v,:] = (X[v,:] @ W^T) * dinv[v]
__global__ void __launch_bounds__(256) k_gemm_scale(
    const float4* __restrict__ X4, const float* __restrict__ W, float4* __restrict__ O4) {
    // sWp[k*32 + j] = pack(W[2j][k], W[2j+1][k])  -> acc[j] holds output cols (2j, 2j+1)
    __shared__ unsigned long long sWp[64 * 32];
    int t = threadIdx.x;
    for (int i = t; i < 2048; i += 256) {
        int k = i >> 5, j = i & 31;
        float lo = W[(2 * j) * 64 + k];
        float hi = W[(2 * j + 1) * 64 + k];
        unsigned long long p;
        asm("mov.b64 %0, {%1, %2};" : "=l"(p) : "f"(lo), "f"(hi));
        sWp[i] = p;
    }
    __syncthreads();
    int r = blockIdx.x * 256 + t;
    if (r >= NN) return;

    unsigned long long acc[32];
#pragma unroll
    for (int j = 0; j < 32; j++) acc[j] = 0ull;

    const float4* xrow = X4 + r * 16;
#pragma unroll 2
    for (int kq = 0; kq < 16; kq++) {
        float4 xv = xrow[kq];
        float xs0 = xv.x, xs1 = xv.y, xs2 = xv.z, xs3 = xv.w;
        float xarr[4] = {xs0, xs1, xs2, xs3};
#pragma unroll
        for (int c = 0; c < 4; c++) {
            unsigned long long x2;
            asm("mov.b64 %0, {%1, %1};" : "=l"(x2) : "f"(xarr[c]));
            const unsigned long long* wrow = &sWp[(kq * 4 + c) * 32];
#pragma unroll
            for (int j = 0; j < 32; j++) {
                asm("fma.rn.f32x2 %0, %1, %2, %0;" : "+l"(acc[j]) : "l"(x2), "l"(wrow[j]));
            }
        }
    }
    float dv = g_dinv[r];
    float4* orow = O4 + r * 16;
#pragma unroll
    for (int jq = 0; jq < 16; jq++) {
        float a, b, c, d;
        asm("mov.b64 {%0, %1}, %2;" : "=f"(a), "=f"(b) : "l"(acc[2 * jq]));
        asm("mov.b64 {%0, %1}, %2;" : "=f"(c), "=f"(d) : "l"(acc[2 * jq + 1]));
        orow[jq] = make_float4(a * dv, b * dv, c * dv, d * dv);
    }
}

// ---------------- aggregation + bias + BN + ReLU (warp per node) ----------------
__global__ void k_agg(const float4* __restrict__ hs4, float* __restrict__ out,
                      const float* __restrict__ bias,
                      const float* __restrict__ bng, const float* __restrict__ bnb,
                      const float* __restrict__ bnm, const float* __restrict__ bnv) {
    int w = (blockIdx.x * blockDim.x + threadIdx.x) >> 5;
    if (w >= NN) return;
    int l = threadIdx.x & 31;
    const float2* base = (const float2*)hs4;  // 32 float2 per row

    float2 acc = base[w * 32 + l];  // self loop: hs[v]
    int s = g_off[w];
    int cnt = g_deg[w];
    int i = 0;
    for (; i + 4 <= cnt; i += 4) {
        int r0 = g_csr[s + i + 0];
        int r1 = g_csr[s + i + 1];
        int r2 = g_csr[s + i + 2];
        int r3 = g_csr[s + i + 3];
        float2 a0 = base[r0 * 32 + l];
        float2 a1 = base[r1 * 32 + l];
        float2 a2 = base[r2 * 32 + l];
        float2 a3 = base[r3 * 32 + l];
        acc.x += (a0.x + a1.x) + (a2.x + a3.x);
        acc.y += (a0.y + a1.y) + (a2.y + a3.y);
    }
    for (; i < cnt; i++) {
        int r = g_csr[s + i];
        float2 a = base[r * 32 + l];
        acc.x += a.x;
        acc.y += a.y;
    }
    float dv = g_dinv[w];
    int c = 2 * l;
    float px = fmaf(acc.x, dv, bias[c]);
    float py = fmaf(acc.y, dv, bias[c + 1]);
    float sx = bng[c] * rsqrtf(bnv[c] + BN_EPS);
    float sy = bng[c + 1] * rsqrtf(bnv[c + 1] + BN_EPS);
    float ox = fmaxf(0.f, fmaf(px - bnm[c], sx, bnb[c]));
    float oy = fmaxf(0.f, fmaf(py - bnm[c + 1], sy, bnb[c + 1]));
    ((float2*)out)[w * 32 + l] = make_float2(ox, oy);
}

// ---------------- pooled sums (segments are contiguous) ----------------
__global__ void k_pool(const float* __restrict__ h) {
    __shared__ float sh[256];
    int g = blockIdx.x;
    int s = g_gstart[g];
    int e = g_gstart[g + 1];
    int t = threadIdx.x;
    int col = t & 63;
    float local = 0.f;
    for (int r = s + blockIdx.y * 4 + (t >> 6); r < e; r += 4 * gridDim.y)
        local += h[r * 64 + col];
    sh[t] = local;
    __syncthreads();
    if (t < 64) {
        float v = sh[t] + sh[t + 64] + sh[t + 128] + sh[t + 192];
        atomicAdd(&g_pool[g * 64 + t], v);
    }
}

// ---------------- MLP head (l1W staged to smem) ----------------
__global__ void k_head(const float* __restrict__ l1W, const float* __restrict__ l1b,
                       const float* __restrict__ l2W, const float* __restrict__ l2b,
                       float* __restrict__ out) {
    __shared__ float sW1[32 * 64];
    __shared__ float sW2[32];
    __shared__ float sB1[32];
    int t = threadIdx.x;  // 64 threads
    for (int i = t; i < 2048; i += 64) sW1[i] = l1W[i];
    if (t < 32) { sW2[t] = l2W[t]; sB1[t] = l1b[t]; }
    __syncthreads();
    if (t >= GG) return;
    int g = t;
    int cnt = g_gstart[g + 1] - g_gstart[g];
    float inv = 1.f / fmaxf((float)cnt, 1.f);
    float p[64];
#pragma unroll
    for (int k = 0; k < 64; k++) p[k] = g_pool[g * 64 + k] * inv;
    float o = l2b[0];
#pragma unroll 4
    for (int j = 0; j < 32; j++) {
        float hsum = sB1[j];
#pragma unroll
        for (int k = 0; k < 64; k++) hsum = fmaf(p[k], sW1[j * 64 + k], hsum);
        o = fmaf(fmaxf(hsum, 0.f), sW2[j], o);
    }
    out[g] = o;
}

// ---------------- launch ----------------
extern "C" void kernel_launch(void* const* d_in, const int* in_sizes, int n_in,
                              void* d_out, int out_size) {
    const float* x      = (const float*)d_in[0];
    const int*   ei     = (const int*)d_in[1];
    const int*   batch  = (const int*)d_in[2];
    const float* W1     = (const float*)d_in[3];
    const float* b1     = (const float*)d_in[4];
    const float* W2     = (const float*)d_in[5];
    const float* b2     = (const float*)d_in[6];
    const float* bn1g   = (const float*)d_in[7];
    const float* bn1b   = (const float*)d_in[8];
    const float* bn1m   = (const float*)d_in[9];
    const float* bn1v   = (const float*)d_in[10];
    const float* bn2g   = (const float*)d_in[11];
    const float* bn2b   = (const float*)d_in[12];
    const float* bn2m   = (const float*)d_in[13];
    const float* bn2v   = (const float*)d_in[14];
    const float* l1W    = (const float*)d_in[15];
    const float* l1b    = (const float*)d_in[16];
    const float* l2W    = (const float*)d_in[17];
    const float* l2b    = (const float*)d_in[18];
    float* out = (float*)d_out;

    float4 *hs4, *buf4;
    cudaGetSymbolAddress((void**)&hs4, g_hs);
    cudaGetSymbolAddress((void**)&buf4, g_buf);

    const int TB = 256;
    int nb_n = (NN + TB - 1) / TB;
    int nb_e = (EE + TB - 1) / TB;
    int nb_scan = (NN + 2047) / 2048;  // 49

    k_zero<<<(NN + 1 + TB - 1) / TB, TB>>>(batch);      // 0
    k_degree<<<nb_e, TB>>>(ei);                          // 1
    k_scan_a<<<nb_scan, 256>>>();                        // 2 (+dinv)
    k_scan_b<<<1, 64>>>(nb_scan);                        // 3
    k_scan_c<<<nb_n, TB>>>();                            // 4
    k_scatter<<<nb_e, TB>>>(ei);                         // 5

    // layer 1
    k_gemm_scale<<<nb_n, 256>>>((const float4*)x, W1, hs4);              // 6
    k_agg<<<(NN * 32 + TB - 1) / TB, TB>>>(hs4, (float*)buf4, b1, bn1g, bn1b, bn1m, bn1v);  // 7
    // layer 2
    k_gemm_scale<<<nb_n, 256>>>((const float4*)buf4, W2, hs4);           // 8
    k_agg<<<(NN * 32 + TB - 1) / TB, TB>>>(hs4, (float*)buf4, b2, bn2g, bn2b, bn2m, bn2v);  // 9

    // pooling + head
    k_pool<<<dim3(GG, 8), 256>>>((const float*)buf4);    // 10
    k_head<<<1, 64>>>(l1W, l1b, l2W, l2b, out);          // 11
}

// round 3
// speedup vs baseline: 1.3110x; 1.1098x over previous
#include <cuda_runtime.h>
#include <cuda_fp16.h>

#define NN 100000
#define EE 1000000
#define HH 64
#define GG 64
#define BN_EPS 1e-5f

// ---------------- scratch (static __device__, no allocations) ----------------
__device__ int     g_deg[NN];        // in-degree (excluding self loop)
__device__ int     g_off[NN];        // CSR offsets; after scatter: END offsets
__device__ int     g_csr[EE];        // CSR: source row per incoming edge, bucketed by dst
__device__ float   g_dinv[NN];       // rsqrt(deg+1)
__device__ __half2 g_hs[NN * 32];    // transformed+scaled features, fp16 (128B/row)
__device__ float2  g_buf[NN * 32];   // layer-1 output (fp32, gemm2 input)
__device__ float   g_pool[GG * 64];  // pooled sums
__device__ int     g_gstart[GG + 1]; // graph segment starts
__device__ int     g_bsum[64];       // scan block sums

// ---------------- init: zero counters + pool, graph bounds from sorted batch ----------------
__global__ void k_zero(const int* __restrict__ batch) {
    int i = blockIdx.x * blockDim.x + threadIdx.x;
    if (i < NN) g_deg[i] = 0;
    if (i < GG * 64) g_pool[i] = 0.f;
    if (i <= NN) {
        int prev = (i == 0) ? -1 : batch[i - 1];
        int cur  = (i < NN) ? batch[i] : GG;
        for (int g = prev + 1; g <= cur && g <= GG; g++) g_gstart[g] = i;
    }
}

// ---------------- degree histogram ----------------
__global__ void k_degree(const int* __restrict__ ei) {
    int e = blockIdx.x * blockDim.x + threadIdx.x;
    if (e >= EE) return;
    atomicAdd(&g_deg[ei[EE + e]], 1);   // col = edge_index[1]
}

// ---------------- scan stage A: per-chunk (2048) exclusive scan + dinv ----------------
__global__ void k_scan_a() {
    __shared__ int sh[256];
    int t = threadIdx.x;
    int base = blockIdx.x * 2048 + t * 8;
    int vals[8];
    int ts = 0;
#pragma unroll
    for (int j = 0; j < 8; j++) {
        int idx = base + j;
        vals[j] = (idx < NN) ? g_deg[idx] : 0;
        if (idx < NN) g_dinv[idx] = rsqrtf((float)(vals[j] + 1));  // +1 self loop
        ts += vals[j];
    }
    sh[t] = ts;
    __syncthreads();
#pragma unroll
    for (int d = 1; d < 256; d <<= 1) {
        int v = (t >= d) ? sh[t - d] : 0;
        __syncthreads();
        sh[t] += v;
        __syncthreads();
    }
    int excl = sh[t] - ts;
    int run = 0;
#pragma unroll
    for (int j = 0; j < 8; j++) {
        int idx = base + j;
        if (idx < NN) g_off[idx] = excl + run;
        run += vals[j];
    }
    if (t == 255) g_bsum[blockIdx.x] = sh[255];
}

// ---------------- scan stage C: add chunk prefix (computed locally per block) ----------------
__global__ void k_scan_c() {
    __shared__ int sv[64];
    __shared__ int pre;
    int t = threadIdx.x;
    int c = blockIdx.x >> 3;  // chunk id of this block's 256 nodes (2048/256=8), c <= 48
    if (t < 64) sv[t] = (t < c) ? g_bsum[t] : 0;
    __syncthreads();
    if (t < 32) {
        int v = sv[t] + sv[t + 32];
#pragma unroll
        for (int d = 16; d > 0; d >>= 1) v += __shfl_down_sync(0xFFFFFFFFu, v, d);
        if (t == 0) pre = v;
    }
    __syncthreads();
    int i = blockIdx.x * 256 + t;
    if (i < NN) g_off[i] += pre;
}

// ---------------- CSR scatter (bumps g_off in place -> end offsets) ----------------
__global__ void k_scatter(const int* __restrict__ ei) {
    int e = blockIdx.x * blockDim.x + threadIdx.x;
    if (e >= EE) return;
    int r = ei[e];
    int c = ei[EE + e];
    int pos = atomicAdd(&g_off[c], 1);
    g_csr[pos] = r;
}

// ---------------- dense transform + row scale, packed f32x2 FMA, fp16 output ----------------
// hs[v,:] = fp16( (X[v,:] @ W^T) * dinv[v] )
__global__ void __launch_bounds__(256) k_gemm_scale(
    const float4* __restrict__ X4, const float* __restrict__ W, __half2* __restrict__ O) {
    // sWp[k*32 + j] = pack(W[2j][k], W[2j+1][k])
    __shared__ unsigned long long sWp[64 * 32];
    int t = threadIdx.x;
    for (int i = t; i < 2048; i += 256) {
        int k = i >> 5, j = i & 31;
        float lo = W[(2 * j) * 64 + k];
        float hi = W[(2 * j + 1) * 64 + k];
        unsigned long long p;
        asm("mov.b64 %0, {%1, %2};" : "=l"(p) : "f"(lo), "f"(hi));
        sWp[i] = p;
    }
    __syncthreads();
    int r = blockIdx.x * 256 + t;
    if (r >= NN) return;

    unsigned long long acc[32];
#pragma unroll
    for (int j = 0; j < 32; j++) acc[j] = 0ull;

    const float4* xrow = X4 + r * 16;
#pragma unroll 2
    for (int kq = 0; kq < 16; kq++) {
        float4 xv = xrow[kq];
        float xarr[4] = {xv.x, xv.y, xv.z, xv.w};
#pragma unroll
        for (int c = 0; c < 4; c++) {
            unsigned long long x2;
            asm("mov.b64 %0, {%1, %1};" : "=l"(x2) : "f"(xarr[c]));
            const unsigned long long* wrow = &sWp[(kq * 4 + c) * 32];
#pragma unroll
            for (int j = 0; j < 32; j++) {
                asm("fma.rn.f32x2 %0, %1, %2, %0;" : "+l"(acc[j]) : "l"(x2), "l"(wrow[j]));
            }
        }
    }
    float dv = g_dinv[r];
    __half2 o[32];
#pragma unroll
    for (int j = 0; j < 32; j++) {
        float a, b;
        asm("mov.b64 {%0, %1}, %2;" : "=f"(a), "=f"(b) : "l"(acc[j]));
        o[j] = __floats2half2_rn(a * dv, b * dv);
    }
    uint4* orow = (uint4*)(O + r * 32);
    const uint4* ov = (const uint4*)o;
#pragma unroll
    for (int q = 0; q < 8; q++) orow[q] = ov[q];
}

// ---------------- aggregation + bias + BN + ReLU; optional fused pooling ----------------
// warp per node; lane l owns channels (2l, 2l+1)
template <bool POOL, int NODES_PER_BLK>
__global__ void k_agg(const __half2* __restrict__ hs, float2* __restrict__ out,
                      const int* __restrict__ batch,
                      const float* __restrict__ bias,
                      const float* __restrict__ bng, const float* __restrict__ bnb,
                      const float* __restrict__ bnm, const float* __restrict__ bnv) {
    __shared__ float sp[2][64];
    int t = threadIdx.x;
    int w0 = blockIdx.x * NODES_PER_BLK;
    int gid0 = 0, gidL = 0;
    if (POOL) {
        if (t < 128) sp[t >> 6][t & 63] = 0.f;
        gid0 = batch[w0];
        int wl = w0 + NODES_PER_BLK - 1;
        gidL = batch[wl < NN ? wl : NN - 1];
        __syncthreads();
    }
    int w = w0 + (t >> 5);
    int l = t & 31;
    float2 acc = make_float2(0.f, 0.f);
    int gid = 0;
    if (w < NN) {
        __half2 sv = hs[w * 32 + l];  // self loop
        float2 f = __half22float2(sv);
        acc = f;
        int e = g_off[w];            // end offset (post-scatter)
        int cnt = g_deg[w];
        int s = e - cnt;
        int i = 0;
        for (; i + 4 <= cnt; i += 4) {
            int r0 = g_csr[s + i + 0];
            int r1 = g_csr[s + i + 1];
            int r2 = g_csr[s + i + 2];
            int r3 = g_csr[s + i + 3];
            float2 a0 = __half22float2(hs[r0 * 32 + l]);
            float2 a1 = __half22float2(hs[r1 * 32 + l]);
            float2 a2 = __half22float2(hs[r2 * 32 + l]);
            float2 a3 = __half22float2(hs[r3 * 32 + l]);
            acc.x += (a0.x + a1.x) + (a2.x + a3.x);
            acc.y += (a0.y + a1.y) + (a2.y + a3.y);
        }
        for (; i < cnt; i++) {
            float2 a = __half22float2(hs[g_csr[s + i] * 32 + l]);
            acc.x += a.x;
            acc.y += a.y;
        }
        float dv = g_dinv[w];
        int c = 2 * l;
        float px = fmaf(acc.x, dv, bias[c]);
        float py = fmaf(acc.y, dv, bias[c + 1]);
        float sx = bng[c] * rsqrtf(bnv[c] + BN_EPS);
        float sy = bng[c + 1] * rsqrtf(bnv[c + 1] + BN_EPS);
        acc.x = fmaxf(0.f, fmaf(px - bnm[c], sx, bnb[c]));
        acc.y = fmaxf(0.f, fmaf(py - bnm[c + 1], sy, bnb[c + 1]));
        if (!POOL) {
            out[w * 32 + l] = acc;
        } else {
            gid = batch[w];
            int slot = gid - gid0;
            int c2 = 2 * l;
            if (slot < 2) {
                atomicAdd(&sp[slot][c2], acc.x);
                atomicAdd(&sp[slot][c2 + 1], acc.y);
            } else {  // safety fallback (graphs smaller than a block span)
                atomicAdd(&g_pool[gid * 64 + c2], acc.x);
                atomicAdd(&g_pool[gid * 64 + c2 + 1], acc.y);
            }
        }
    }
    if (POOL) {
        __syncthreads();
        if (t < 128) {
            int s = t >> 6, ch = t & 63;
            int gg = gid0 + s;
            if (gg <= gidL && gg < GG) atomicAdd(&g_pool[gg * 64 + ch], sp[s][ch]);
        }
    }
}

// ---------------- MLP head ----------------
__global__ void k_head(const float* __restrict__ l1W, const float* __restrict__ l1b,
                       const float* __restrict__ l2W, const float* __restrict__ l2b,
                       float* __restrict__ out) {
    __shared__ float sW1[32 * 64];
    __shared__ float sW2[32];
    __shared__ float sB1[32];
    int t = threadIdx.x;  // 64 threads
    for (int i = t; i < 2048; i += 64) sW1[i] = l1W[i];
    if (t < 32) { sW2[t] = l2W[t]; sB1[t] = l1b[t]; }
    __syncthreads();
    if (t >= GG) return;
    int g = t;
    int cnt = g_gstart[g + 1] - g_gstart[g];
    float inv = 1.f / fmaxf((float)cnt, 1.f);
    float p[64];
#pragma unroll
    for (int k = 0; k < 64; k++) p[k] = g_pool[g * 64 + k] * inv;
    float o = l2b[0];
#pragma unroll 4
    for (int j = 0; j < 32; j++) {
        float hsum = sB1[j];
#pragma unroll
        for (int k = 0; k < 64; k++) hsum = fmaf(p[k], sW1[j * 64 + k], hsum);
        o = fmaf(fmaxf(hsum, 0.f), sW2[j], o);
    }
    out[g] = o;
}

// ---------------- launch ----------------
extern "C" void kernel_launch(void* const* d_in, const int* in_sizes, int n_in,
                              void* d_out, int out_size) {
    const float* x      = (const float*)d_in[0];
    const int*   ei     = (const int*)d_in[1];
    const int*   batch  = (const int*)d_in[2];
    const float* W1     = (const float*)d_in[3];
    const float* b1     = (const float*)d_in[4];
    const float* W2     = (const float*)d_in[5];
    const float* b2     = (const float*)d_in[6];
    const float* bn1g   = (const float*)d_in[7];
    const float* bn1b   = (const float*)d_in[8];
    const float* bn1m   = (const float*)d_in[9];
    const float* bn1v   = (const float*)d_in[10];
    const float* bn2g   = (const float*)d_in[11];
    const float* bn2b   = (const float*)d_in[12];
    const float* bn2m   = (const float*)d_in[13];
    const float* bn2v   = (const float*)d_in[14];
    const float* l1W    = (const float*)d_in[15];
    const float* l1b    = (const float*)d_in[16];
    const float* l2W    = (const float*)d_in[17];
    const float* l2b    = (const float*)d_in[18];
    float* out = (float*)d_out;

    __half2* hs;
    float2* buf;
    cudaGetSymbolAddress((void**)&hs, g_hs);
    cudaGetSymbolAddress((void**)&buf, g_buf);

    const int TB = 256;
    int nb_n = (NN + TB - 1) / TB;
    int nb_e = (EE + TB - 1) / TB;
    int nb_scan = (NN + 2047) / 2048;  // 49

    k_zero<<<(NN + 1 + TB - 1) / TB, TB>>>(batch);              // 0
    k_degree<<<nb_e, TB>>>(ei);                                  // 1
    k_scan_a<<<nb_scan, 256>>>();                                // 2
    k_gemm_scale<<<nb_n, 256>>>((const float4*)x, W1, hs);       // 3  <- ncu capture lands here
    k_scan_c<<<nb_n, 256>>>();                                   // 4
    k_scatter<<<nb_e, TB>>>(ei);                                 // 5

    // layer 1: agg -> fp32 buf
    k_agg<false, 8><<<(NN + 7) / 8, 256>>>(hs, buf, batch, b1, bn1g, bn1b, bn1m, bn1v);   // 6
    // layer 2: transform
    k_gemm_scale<<<nb_n, 256>>>((const float4*)buf, W2, hs);     // 7
    // layer 2: agg + fused pooling (no buf write)
    k_agg<true, 16><<<NN / 16, 512>>>(hs, nullptr, batch, b2, bn2g, bn2b, bn2m, bn2v);    // 8

    k_head<<<1, 64>>>(l1W, l1b, l2W, l2b, out);                  // 9
}

// round 4
// speedup vs baseline: 1.3986x; 1.0668x over previous
#include <cuda_runtime.h>
#include <cuda_fp16.h>

#define NN 100000
#define EE 1000000
#define HH 64
#define GG 64
#define BN_EPS 1e-5f

// ---------------- scratch (static __device__, no allocations) ----------------
__device__ int     g_deg[NN];        // in-degree (excluding self loop)
__device__ int     g_off[NN];        // CSR offsets; after scatter: END offsets
__device__ int     g_csr[EE];        // CSR: source row per incoming edge, bucketed by dst
__device__ float   g_dinv[NN];       // rsqrt(deg+1)
__device__ __half2 g_hs[NN * 32];    // transformed+scaled features, fp16 (128B/row)
__device__ float2  g_buf[NN * 32];   // layer-1 output (fp32, gemm2 input)
__device__ float   g_pool[GG * 64];  // pooled sums
__device__ int     g_gstart[GG + 1]; // graph segment starts
__device__ int     g_bsum[64];       // scan block sums

// ---------------- init: zero counters + pool, graph bounds from sorted batch ----------------
__global__ void k_zero(const int* __restrict__ batch) {
    int i = blockIdx.x * blockDim.x + threadIdx.x;
    if (i < NN) g_deg[i] = 0;
    if (i < GG * 64) g_pool[i] = 0.f;
    if (i <= NN) {
        int prev = (i == 0) ? -1 : batch[i - 1];
        int cur  = (i < NN) ? batch[i] : GG;
        for (int g = prev + 1; g <= cur && g <= GG; g++) g_gstart[g] = i;
    }
}

// ---------------- degree histogram ----------------
__global__ void k_degree(const int* __restrict__ ei) {
    int e = blockIdx.x * blockDim.x + threadIdx.x;
    if (e >= EE) return;
    atomicAdd(&g_deg[ei[EE + e]], 1);   // col = edge_index[1]
}

// ---------------- scan stage A: per-chunk (2048) exclusive scan + dinv ----------------
__global__ void k_scan_a() {
    __shared__ int sh[256];
    int t = threadIdx.x;
    int base = blockIdx.x * 2048 + t * 8;
    int vals[8];
    int ts = 0;
#pragma unroll
    for (int j = 0; j < 8; j++) {
        int idx = base + j;
        vals[j] = (idx < NN) ? g_deg[idx] : 0;
        if (idx < NN) g_dinv[idx] = rsqrtf((float)(vals[j] + 1));  // +1 self loop
        ts += vals[j];
    }
    sh[t] = ts;
    __syncthreads();
#pragma unroll
    for (int d = 1; d < 256; d <<= 1) {
        int v = (t >= d) ? sh[t - d] : 0;
        __syncthreads();
        sh[t] += v;
        __syncthreads();
    }
    int excl = sh[t] - ts;
    int run = 0;
#pragma unroll
    for (int j = 0; j < 8; j++) {
        int idx = base + j;
        if (idx < NN) g_off[idx] = excl + run;
        run += vals[j];
    }
    if (t == 255) g_bsum[blockIdx.x] = sh[255];
}

// ---------------- scan stage C: add chunk prefix (computed locally per block) ----------------
__global__ void k_scan_c() {
    __shared__ int sv[64];
    __shared__ int pre;
    int t = threadIdx.x;
    int c = blockIdx.x >> 3;  // chunk id (2048/256=8 blocks per chunk)
    if (t < 64) sv[t] = (t < c) ? g_bsum[t] : 0;
    __syncthreads();
    if (t < 32) {
        int v = sv[t] + sv[t + 32];
#pragma unroll
        for (int d = 16; d > 0; d >>= 1) v += __shfl_down_sync(0xFFFFFFFFu, v, d);
        if (t == 0) pre = v;
    }
    __syncthreads();
    int i = blockIdx.x * 256 + t;
    if (i < NN) g_off[i] += pre;
}

// ---------------- CSR scatter (bumps g_off in place -> end offsets) ----------------
__global__ void k_scatter(const int* __restrict__ ei) {
    int e = blockIdx.x * blockDim.x + threadIdx.x;
    if (e >= EE) return;
    int r = ei[e];
    int c = ei[EE + e];
    int pos = atomicAdd(&g_off[c], 1);
    g_csr[pos] = r;
}

// ---------------- dense transform + row scale, f32x2 FMA, fp16 output ----------------
// hs[v,:] = fp16( (X[v,:] @ W^T) * dinv[v] )
// 2 rows/thread x 32 channels/thread; weights via LDS.128 (1 LDS : 4 FFMA2)
__global__ void __launch_bounds__(256) k_gemm_scale(
    const float4* __restrict__ X4, const float* __restrict__ W, __half2* __restrict__ O) {
    // sWp[k*16 + q] packs channels 4q..4q+3 of W column k:
    //   .x = pack(W[4q][k], W[4q+1][k]) ; .y = pack(W[4q+2][k], W[4q+3][k])
    __shared__ ulonglong2 sWp[64 * 16];
    int t = threadIdx.x;
    for (int i = t; i < 1024; i += 256) {
        int k = i >> 4, q = i & 15;
        float a = W[(4 * q + 0) * 64 + k];
        float b = W[(4 * q + 1) * 64 + k];
        float c = W[(4 * q + 2) * 64 + k];
        float d = W[(4 * q + 3) * 64 + k];
        unsigned long long lo, hi;
        asm("mov.b64 %0, {%1, %2};" : "=l"(lo) : "f"(a), "f"(b));
        asm("mov.b64 %0, {%1, %2};" : "=l"(hi) : "f"(c), "f"(d));
        sWp[i] = make_ulonglong2(lo, hi);
    }
    __syncthreads();

    int tx = t & 127;          // row slot
    int ty = t >> 7;           // channel half (0 or 1)
    int r0 = blockIdx.x * 256 + tx;
    if (r0 >= NN) return;
    int r1 = r0 + 128;
    bool v1 = r1 < NN;
    int rl1 = v1 ? r1 : r0;

    unsigned long long acc0[16], acc1[16];
#pragma unroll
    for (int j = 0; j < 16; j++) { acc0[j] = 0ull; acc1[j] = 0ull; }

    const float4* x0 = X4 + (size_t)r0 * 16;
    const float4* x1 = X4 + (size_t)rl1 * 16;
#pragma unroll 2
    for (int kq = 0; kq < 16; kq++) {
        float4 a0 = x0[kq];
        float4 a1 = x1[kq];
        float xa0[4] = {a0.x, a0.y, a0.z, a0.w};
        float xa1[4] = {a1.x, a1.y, a1.z, a1.w};
#pragma unroll
        for (int c = 0; c < 4; c++) {
            int k = kq * 4 + c;
            unsigned long long p0, p1;
            asm("mov.b64 %0, {%1, %1};" : "=l"(p0) : "f"(xa0[c]));
            asm("mov.b64 %0, {%1, %1};" : "=l"(p1) : "f"(xa1[c]));
            const ulonglong2* wrow = &sWp[k * 16 + ty * 8];
#pragma unroll
            for (int q = 0; q < 8; q++) {
                ulonglong2 w = wrow[q];  // LDS.128 broadcast
                asm("fma.rn.f32x2 %0, %1, %2, %0;" : "+l"(acc0[2 * q])     : "l"(p0), "l"(w.x));
                asm("fma.rn.f32x2 %0, %1, %2, %0;" : "+l"(acc0[2 * q + 1]) : "l"(p0), "l"(w.y));
                asm("fma.rn.f32x2 %0, %1, %2, %0;" : "+l"(acc1[2 * q])     : "l"(p1), "l"(w.x));
                asm("fma.rn.f32x2 %0, %1, %2, %0;" : "+l"(acc1[2 * q + 1]) : "l"(p1), "l"(w.y));
            }
        }
    }

    float dv0 = g_dinv[r0];
    float dv1 = g_dinv[rl1];
    __half2 o0[16], o1[16];
#pragma unroll
    for (int j = 0; j < 16; j++) {
        float a, b;
        asm("mov.b64 {%0, %1}, %2;" : "=f"(a), "=f"(b) : "l"(acc0[j]));
        o0[j] = __floats2half2_rn(a * dv0, b * dv0);
        asm("mov.b64 {%0, %1}, %2;" : "=f"(a), "=f"(b) : "l"(acc1[j]));
        o1[j] = __floats2half2_rn(a * dv1, b * dv1);
    }
    uint4* d0 = (uint4*)(O + (size_t)r0 * 32 + ty * 16);
    const uint4* s0 = (const uint4*)o0;
#pragma unroll
    for (int q = 0; q < 4; q++) d0[q] = s0[q];
    if (v1) {
        uint4* d1 = (uint4*)(O + (size_t)r1 * 32 + ty * 16);
        const uint4* s1 = (const uint4*)o1;
#pragma unroll
        for (int q = 0; q < 4; q++) d1[q] = s1[q];
    }
}

// ---------------- aggregation + bias + BN + ReLU; optional fused pooling ----------------
// warp per node; lane l owns channels (2l, 2l+1)
template <bool POOL, int NODES_PER_BLK>
__global__ void k_agg(const __half2* __restrict__ hs, float2* __restrict__ out,
                      const int* __restrict__ batch,
                      const float* __restrict__ bias,
                      const float* __restrict__ bng, const float* __restrict__ bnb,
                      const float* __restrict__ bnm, const float* __restrict__ bnv) {
    __shared__ float sp[2][64];
    int t = threadIdx.x;
    int w0 = blockIdx.x * NODES_PER_BLK;
    int gid0 = 0, gidL = 0;
    if (POOL) {
        if (t < 128) sp[t >> 6][t & 63] = 0.f;
        gid0 = batch[w0];
        int wl = w0 + NODES_PER_BLK - 1;
        gidL = batch[wl < NN ? wl : NN - 1];
        __syncthreads();
    }
    int w = w0 + (t >> 5);
    int l = t & 31;
    float2 acc = make_float2(0.f, 0.f);
    if (w < NN) {
        float2 f = __half22float2(hs[w * 32 + l]);  // self loop
        acc = f;
        int e = g_off[w];            // end offset (post-scatter)
        int cnt = g_deg[w];
        int s = e - cnt;
        int i = 0;
        for (; i + 4 <= cnt; i += 4) {
            int r0 = g_csr[s + i + 0];
            int r1 = g_csr[s + i + 1];
            int r2 = g_csr[s + i + 2];
            int r3 = g_csr[s + i + 3];
            float2 a0 = __half22float2(hs[r0 * 32 + l]);
            float2 a1 = __half22float2(hs[r1 * 32 + l]);
            float2 a2 = __half22float2(hs[r2 * 32 + l]);
            float2 a3 = __half22float2(hs[r3 * 32 + l]);
            acc.x += (a0.x + a1.x) + (a2.x + a3.x);
            acc.y += (a0.y + a1.y) + (a2.y + a3.y);
        }
        for (; i < cnt; i++) {
            float2 a = __half22float2(hs[g_csr[s + i] * 32 + l]);
            acc.x += a.x;
            acc.y += a.y;
        }
        float dv = g_dinv[w];
        int c = 2 * l;
        float px = fmaf(acc.x, dv, bias[c]);
        float py = fmaf(acc.y, dv, bias[c + 1]);
        float sx = bng[c] * rsqrtf(bnv[c] + BN_EPS);
        float sy = bng[c + 1] * rsqrtf(bnv[c + 1] + BN_EPS);
        acc.x = fmaxf(0.f, fmaf(px - bnm[c], sx, bnb[c]));
        acc.y = fmaxf(0.f, fmaf(py - bnm[c + 1], sy, bnb[c + 1]));
        if (!POOL) {
            out[w * 32 + l] = acc;
        } else {
            int gid = batch[w];
            int slot = gid - gid0;
            int c2 = 2 * l;
            if (slot < 2) {
                atomicAdd(&sp[slot][c2], acc.x);
                atomicAdd(&sp[slot][c2 + 1], acc.y);
            } else {  // safety fallback (block spans >2 graphs)
                atomicAdd(&g_pool[gid * 64 + c2], acc.x);
                atomicAdd(&g_pool[gid * 64 + c2 + 1], acc.y);
            }
        }
    }
    if (POOL) {
        __syncthreads();
        if (t < 128) {
            int s = t >> 6, ch = t & 63;
            int gg = gid0 + s;
            if (gg <= gidL && gg < GG) atomicAdd(&g_pool[gg * 64 + ch], sp[s][ch]);
        }
    }
}

// ---------------- MLP head ----------------
__global__ void k_head(const float* __restrict__ l1W, const float* __restrict__ l1b,
                       const float* __restrict__ l2W, const float* __restrict__ l2b,
                       float* __restrict__ out) {
    __shared__ float sW1[32 * 64];
    __shared__ float sW2[32];
    __shared__ float sB1[32];
    int t = threadIdx.x;  // 64 threads
    for (int i = t; i < 2048; i += 64) sW1[i] = l1W[i];
    if (t < 32) { sW2[t] = l2W[t]; sB1[t] = l1b[t]; }
    __syncthreads();
    if (t >= GG) return;
    int g = t;
    int cnt = g_gstart[g + 1] - g_gstart[g];
    float inv = 1.f / fmaxf((float)cnt, 1.f);
    float p[64];
#pragma unroll
    for (int k = 0; k < 64; k++) p[k] = g_pool[g * 64 + k] * inv;
    float o = l2b[0];
#pragma unroll 4
    for (int j = 0; j < 32; j++) {
        float hsum = sB1[j];
#pragma unroll
        for (int k = 0; k < 64; k++) hsum = fmaf(p[k], sW1[j * 64 + k], hsum);
        o = fmaf(fmaxf(hsum, 0.f), sW2[j], o);
    }
    out[g] = o;
}

// ---------------- launch ----------------
extern "C" void kernel_launch(void* const* d_in, const int* in_sizes, int n_in,
                              void* d_out, int out_size) {
    const float* x      = (const float*)d_in[0];
    const int*   ei     = (const int*)d_in[1];
    const int*   batch  = (const int*)d_in[2];
    const float* W1     = (const float*)d_in[3];
    const float* b1     = (const float*)d_in[4];
    const float* W2     = (const float*)d_in[5];
    const float* b2     = (const float*)d_in[6];
    const float* bn1g   = (const float*)d_in[7];
    const float* bn1b   = (const float*)d_in[8];
    const float* bn1m   = (const float*)d_in[9];
    const float* bn1v   = (const float*)d_in[10];
    const float* bn2g   = (const float*)d_in[11];
    const float* bn2b   = (const float*)d_in[12];
    const float* bn2m   = (const float*)d_in[13];
    const float* bn2v   = (const float*)d_in[14];
    const float* l1W    = (const float*)d_in[15];
    const float* l1b    = (const float*)d_in[16];
    const float* l2W    = (const float*)d_in[17];
    const float* l2b    = (const float*)d_in[18];
    float* out = (float*)d_out;

    __half2* hs;
    float2* buf;
    cudaGetSymbolAddress((void**)&hs, g_hs);
    cudaGetSymbolAddress((void**)&buf, g_buf);

    const int TB = 256;
    int nb_n = (NN + TB - 1) / TB;
    int nb_e = (EE + TB - 1) / TB;
    int nb_scan = (NN + 2047) / 2048;  // 49

    k_zero<<<(NN + 1 + TB - 1) / TB, TB>>>(batch);              // 0
    k_degree<<<nb_e, TB>>>(ei);                                  // 1
    k_scan_a<<<nb_scan, 256>>>();                                // 2
    k_gemm_scale<<<nb_n, 256>>>((const float4*)x, W1, hs);       // 3  <- ncu capture lands here
    k_scan_c<<<nb_n, 256>>>();                                   // 4
    k_scatter<<<nb_e, TB>>>(ei);                                 // 5

    // layer 1: agg -> fp32 buf
    k_agg<false, 8><<<(NN + 7) / 8, 256>>>(hs, buf, batch, b1, bn1g, bn1b, bn1m, bn1v);   // 6
    // layer 2: transform
    k_gemm_scale<<<nb_n, 256>>>((const float4*)buf, W2, hs);     // 7
    // layer 2: agg + fused pooling (no buf write)
    k_agg<true, 16><<<NN / 16, 512>>>(hs, nullptr, batch, b2, bn2g, bn2b, bn2m, bn2v);    // 8

    k_head<<<1, 64>>>(l1W, l1b, l2W, l2b, out);                  // 9
}

// round 5
// speedup vs baseline: 1.7236x; 1.2324x over previous
#include <cuda_runtime.h>
#include <cuda_fp16.h>

#define NN 100000
#define EE 1000000
#define HH 64
#define GG 64
#define BN_EPS 1e-5f

// ---------------- scratch (static __device__, no allocations) ----------------
__device__ int     g_deg[NN];        // in-degree (excluding self loop)
__device__ int     g_off[NN];        // CSR offsets; after scatter: END offsets
__device__ int     g_csr[EE];        // CSR: source row per incoming edge, bucketed by dst
__device__ float   g_dinv[NN];       // rsqrt(deg+1)
__device__ __half2 g_hs[NN * 32];    // transformed+scaled features, fp16 (128B/row)
__device__ float2  g_buf[NN * 32];   // layer-1 output (fp32, gemm2 input)
__device__ float   g_pool[GG * 64];  // pooled sums
__device__ int     g_gstart[GG + 1]; // graph segment starts
__device__ int     g_bsum[64];       // scan block sums

// ---------------- init ----------------
__global__ void k_zero(const int* __restrict__ batch) {
    int i = blockIdx.x * blockDim.x + threadIdx.x;
    if (i < NN) g_deg[i] = 0;
    if (i < GG * 64) g_pool[i] = 0.f;
    if (i <= NN) {
        int prev = (i == 0) ? -1 : batch[i - 1];
        int cur  = (i < NN) ? batch[i] : GG;
        for (int g = prev + 1; g <= cur && g <= GG; g++) g_gstart[g] = i;
    }
}

// ---------------- degree histogram ----------------
__global__ void k_degree(const int* __restrict__ ei) {
    int e = blockIdx.x * blockDim.x + threadIdx.x;
    if (e >= EE) return;
    atomicAdd(&g_deg[ei[EE + e]], 1);   // col = edge_index[1]
}

// ---------------- scan stage A ----------------
__global__ void k_scan_a() {
    __shared__ int sh[256];
    int t = threadIdx.x;
    int base = blockIdx.x * 2048 + t * 8;
    int vals[8];
    int ts = 0;
#pragma unroll
    for (int j = 0; j < 8; j++) {
        int idx = base + j;
        vals[j] = (idx < NN) ? g_deg[idx] : 0;
        if (idx < NN) g_dinv[idx] = rsqrtf((float)(vals[j] + 1));
        ts += vals[j];
    }
    sh[t] = ts;
    __syncthreads();
#pragma unroll
    for (int d = 1; d < 256; d <<= 1) {
        int v = (t >= d) ? sh[t - d] : 0;
        __syncthreads();
        sh[t] += v;
        __syncthreads();
    }
    int excl = sh[t] - ts;
    int run = 0;
#pragma unroll
    for (int j = 0; j < 8; j++) {
        int idx = base + j;
        if (idx < NN) g_off[idx] = excl + run;
        run += vals[j];
    }
    if (t == 255) g_bsum[blockIdx.x] = sh[255];
}

// ---------------- scan stage C ----------------
__global__ void k_scan_c() {
    __shared__ int sv[64];
    __shared__ int pre;
    int t = threadIdx.x;
    int c = blockIdx.x >> 3;
    if (t < 64) sv[t] = (t < c) ? g_bsum[t] : 0;
    __syncthreads();
    if (t < 32) {
        int v = sv[t] + sv[t + 32];
#pragma unroll
        for (int d = 16; d > 0; d >>= 1) v += __shfl_down_sync(0xFFFFFFFFu, v, d);
        if (t == 0) pre = v;
    }
    __syncthreads();
    int i = blockIdx.x * 256 + t;
    if (i < NN) g_off[i] += pre;
}

// ---------------- CSR scatter ----------------
__global__ void k_scatter(const int* __restrict__ ei) {
    int e = blockIdx.x * blockDim.x + threadIdx.x;
    if (e >= EE) return;
    int r = ei[e];
    int c = ei[EE + e];
    int pos = atomicAdd(&g_off[c], 1);
    g_csr[pos] = r;
}

// ---------------- tf32 helper ----------------
__device__ __forceinline__ unsigned to_tf32(float f) {
    unsigned r;
    asm("cvt.rna.tf32.f32 %0, %1;" : "=r"(r) : "f"(f));
    return r;
}

// ---------------- GEMM via mma.sync m16n8k8 tf32 ----------------
// hs[v,:] = fp16( (X[v,:] @ W^T) * dinv[v] )
// Block: 128 thr / 4 warps / 64 rows. Warp w does rows [base+16w, base+16w+16).
__global__ void __launch_bounds__(128) k_gemm_mma(
    const float4* __restrict__ X4, const float* __restrict__ W, __half2* __restrict__ O) {
    // A fragments: sA[warp][kt][lane][reg]; B fragments: sB[kt][nt][lane][reg]
    __shared__ unsigned sA[4][8][32][4];   // 16KB
    __shared__ unsigned sB[8][8][32][2];   // 16KB
    int tid = threadIdx.x;
    int base = blockIdx.x * 64;

    // stage B = W (n=out channel, k=in channel), fragment layout for mma .col:
    //   b0: k = lane%4, n = lane/4 ; b1: k = lane%4+4
    for (int i = tid; i < 4096; i += 128) {
        int n = i >> 6, k = i & 63;
        sB[k >> 3][n >> 3][(n & 7) * 4 + (k & 3)][(k >> 2) & 1] = to_tf32(W[i]);
    }
    // stage A = X rows, fragment layout .row:
    //   a0:(g,t) a1:(g+8,t) a2:(g,t+4) a3:(g+8,t+4), g=lane/4, t=lane%4
    for (int i = tid; i < 1024; i += 128) {
        int r = i >> 4, j = i & 15;
        int R = base + r;
        float4 v = make_float4(0.f, 0.f, 0.f, 0.f);
        if (R < NN) v = X4[(size_t)R * 16 + j];
        int w = r >> 4, rr = r & 15;
        int c0 = j * 4;
        int kt = c0 >> 3;
        int reg = ((rr >> 3) & 1) | (((c0 >> 2) & 1) << 1);
        int lb = (rr & 7) * 4;
        sA[w][kt][lb + 0][reg] = to_tf32(v.x);
        sA[w][kt][lb + 1][reg] = to_tf32(v.y);
        sA[w][kt][lb + 2][reg] = to_tf32(v.z);
        sA[w][kt][lb + 3][reg] = to_tf32(v.w);
    }
    __syncthreads();

    int lane = tid & 31;
    int w = tid >> 5;
    float d[8][4];
#pragma unroll
    for (int nt = 0; nt < 8; nt++)
#pragma unroll
        for (int j = 0; j < 4; j++) d[nt][j] = 0.f;

#pragma unroll
    for (int kt = 0; kt < 8; kt++) {
        uint4 a = *(const uint4*)&sA[w][kt][lane][0];   // LDS.128, conflict-free
#pragma unroll
        for (int nt = 0; nt < 8; nt++) {
            uint2 b = *(const uint2*)&sB[kt][nt][lane][0];  // LDS.64, conflict-free
            asm volatile(
                "mma.sync.aligned.m16n8k8.row.col.f32.tf32.tf32.f32 "
                "{%0,%1,%2,%3}, {%4,%5,%6,%7}, {%8,%9}, {%0,%1,%2,%3};"
                : "+f"(d[nt][0]), "+f"(d[nt][1]), "+f"(d[nt][2]), "+f"(d[nt][3])
                : "r"(a.x), "r"(a.y), "r"(a.z), "r"(a.w), "r"(b.x), "r"(b.y));
        }
    }

    // epilogue: D fragment c0,c1: (row=g, cols 2t,2t+1); c2,c3: (row=g+8)
    int g = lane >> 2, t4 = lane & 3;
    int row0 = base + w * 16 + g;
    int row1 = row0 + 8;
    bool v0 = row0 < NN, v1 = row1 < NN;
    float dv0 = v0 ? g_dinv[row0] : 0.f;
    float dv1 = v1 ? g_dinv[row1] : 0.f;
#pragma unroll
    for (int nt = 0; nt < 8; nt++) {
        int cp = nt * 4 + t4;  // half2 column index
        if (v0) O[(size_t)row0 * 32 + cp] = __floats2half2_rn(d[nt][0] * dv0, d[nt][1] * dv0);
        if (v1) O[(size_t)row1 * 32 + cp] = __floats2half2_rn(d[nt][2] * dv1, d[nt][3] * dv1);
    }
}

// ---------------- aggregation + bias + BN + ReLU; optional fused pooling ----------------
template <bool POOL, int NODES_PER_BLK>
__global__ void k_agg(const __half2* __restrict__ hs, float2* __restrict__ out,
                      const int* __restrict__ batch,
                      const float* __restrict__ bias,
                      const float* __restrict__ bng, const float* __restrict__ bnb,
                      const float* __restrict__ bnm, const float* __restrict__ bnv) {
    __shared__ float sp[2][64];
    int t = threadIdx.x;
    int w0 = blockIdx.x * NODES_PER_BLK;
    int gid0 = 0, gidL = 0;
    if (POOL) {
        if (t < 128) sp[t >> 6][t & 63] = 0.f;
        gid0 = batch[w0];
        int wl = w0 + NODES_PER_BLK - 1;
        gidL = batch[wl < NN ? wl : NN - 1];
        __syncthreads();
    }
    int w = w0 + (t >> 5);
    int l = t & 31;
    float2 acc = make_float2(0.f, 0.f);
    if (w < NN) {
        float2 f = __half22float2(hs[w * 32 + l]);  // self loop
        acc = f;
        int e = g_off[w];
        int cnt = g_deg[w];
        int s = e - cnt;
        int i = 0;
        for (; i + 4 <= cnt; i += 4) {
            int r0 = g_csr[s + i + 0];
            int r1 = g_csr[s + i + 1];
            int r2 = g_csr[s + i + 2];
            int r3 = g_csr[s + i + 3];
            float2 a0 = __half22float2(hs[r0 * 32 + l]);
            float2 a1 = __half22float2(hs[r1 * 32 + l]);
            float2 a2 = __half22float2(hs[r2 * 32 + l]);
            float2 a3 = __half22float2(hs[r3 * 32 + l]);
            acc.x += (a0.x + a1.x) + (a2.x + a3.x);
            acc.y += (a0.y + a1.y) + (a2.y + a3.y);
        }
        for (; i < cnt; i++) {
            float2 a = __half22float2(hs[g_csr[s + i] * 32 + l]);
            acc.x += a.x;
            acc.y += a.y;
        }
        float dv = g_dinv[w];
        int c = 2 * l;
        float px = fmaf(acc.x, dv, bias[c]);
        float py = fmaf(acc.y, dv, bias[c + 1]);
        float sx = bng[c] * rsqrtf(bnv[c] + BN_EPS);
        float sy = bng[c + 1] * rsqrtf(bnv[c + 1] + BN_EPS);
        acc.x = fmaxf(0.f, fmaf(px - bnm[c], sx, bnb[c]));
        acc.y = fmaxf(0.f, fmaf(py - bnm[c + 1], sy, bnb[c + 1]));
        if (!POOL) {
            out[w * 32 + l] = acc;
        } else {
            int gid = batch[w];
            int slot = gid - gid0;
            int c2 = 2 * l;
            if (slot < 2) {
                atomicAdd(&sp[slot][c2], acc.x);
                atomicAdd(&sp[slot][c2 + 1], acc.y);
            } else {
                atomicAdd(&g_pool[gid * 64 + c2], acc.x);
                atomicAdd(&g_pool[gid * 64 + c2 + 1], acc.y);
            }
        }
    }
    if (POOL) {
        __syncthreads();
        if (t < 128) {
            int s = t >> 6, ch = t & 63;
            int gg = gid0 + s;
            if (gg <= gidL && gg < GG) atomicAdd(&g_pool[gg * 64 + ch], sp[s][ch]);
        }
    }
}

// ---------------- MLP head ----------------
__global__ void k_head(const float* __restrict__ l1W, const float* __restrict__ l1b,
                       const float* __restrict__ l2W, const float* __restrict__ l2b,
                       float* __restrict__ out) {
    __shared__ float sW1[32 * 64];
    __shared__ float sW2[32];
    __shared__ float sB1[32];
    int t = threadIdx.x;  // 64 threads
    for (int i = t; i < 2048; i += 64) sW1[i] = l1W[i];
    if (t < 32) { sW2[t] = l2W[t]; sB1[t] = l1b[t]; }
    __syncthreads();
    if (t >= GG) return;
    int g = t;
    int cnt = g_gstart[g + 1] - g_gstart[g];
    float inv = 1.f / fmaxf((float)cnt, 1.f);
    float p[64];
#pragma unroll
    for (int k = 0; k < 64; k++) p[k] = g_pool[g * 64 + k] * inv;
    float o = l2b[0];
#pragma unroll 4
    for (int j = 0; j < 32; j++) {
        float hsum = sB1[j];
#pragma unroll
        for (int k = 0; k < 64; k++) hsum = fmaf(p[k], sW1[j * 64 + k], hsum);
        o = fmaf(fmaxf(hsum, 0.f), sW2[j], o);
    }
    out[g] = o;
}

// ---------------- launch ----------------
extern "C" void kernel_launch(void* const* d_in, const int* in_sizes, int n_in,
                              void* d_out, int out_size) {
    const float* x      = (const float*)d_in[0];
    const int*   ei     = (const int*)d_in[1];
    const int*   batch  = (const int*)d_in[2];
    const float* W1     = (const float*)d_in[3];
    const float* b1     = (const float*)d_in[4];
    const float* W2     = (const float*)d_in[5];
    const float* b2     = (const float*)d_in[6];
    const float* bn1g   = (const float*)d_in[7];
    const float* bn1b   = (const float*)d_in[8];
    const float* bn1m   = (const float*)d_in[9];
    const float* bn1v   = (const float*)d_in[10];
    const float* bn2g   = (const float*)d_in[11];
    const float* bn2b   = (const float*)d_in[12];
    const float* bn2m   = (const float*)d_in[13];
    const float* bn2v   = (const float*)d_in[14];
    const float* l1W    = (const float*)d_in[15];
    const float* l1b    = (const float*)d_in[16];
    const float* l2W    = (const float*)d_in[17];
    const float* l2b    = (const float*)d_in[18];
    float* out = (float*)d_out;

    __half2* hs;
    float2* buf;
    cudaGetSymbolAddress((void**)&hs, g_hs);
    cudaGetSymbolAddress((void**)&buf, g_buf);

    const int TB = 256;
    int nb_e = (EE + TB - 1) / TB;
    int nb_scan = (NN + 2047) / 2048;   // 49
    int nb_gemm = (NN + 63) / 64;       // 1563

    k_zero<<<(NN + 1 + TB - 1) / TB, TB>>>(batch);              // 0
    k_degree<<<nb_e, TB>>>(ei);                                  // 1
    k_scan_a<<<nb_scan, 256>>>();                                // 2
    k_gemm_mma<<<nb_gemm, 128>>>((const float4*)x, W1, hs);      // 3  <- ncu capture lands here
    k_scan_c<<<(NN + 255) / 256, 256>>>();                       // 4
    k_scatter<<<nb_e, TB>>>(ei);                                 // 5

    // layer 1: agg -> fp32 buf
    k_agg<false, 8><<<(NN + 7) / 8, 256>>>(hs, buf, batch, b1, bn1g, bn1b, bn1m, bn1v);   // 6
    // layer 2: transform
    k_gemm_mma<<<nb_gemm, 128>>>((const float4*)buf, W2, hs);    // 7
    // layer 2: agg + fused pooling
    k_agg<true, 16><<<NN / 16, 512>>>(hs, nullptr, batch, b2, bn2g, bn2b, bn2m, bn2v);    // 8

    k_head<<<1, 64>>>(l1W, l1b, l2W, l2b, out);                  // 9
}

// round 6
// speedup vs baseline: 1.9112x; 1.1088x over previous
#include <cuda_runtime.h>
#include <cuda_fp16.h>

#define NN 100000
#define EE 1000000
#define HH 64
#define GG 64
#define BN_EPS 1e-5f

// ---------------- scratch (static __device__, no allocations) ----------------
__device__ int      g_deg[NN];        // in-degree (excluding self loop)
__device__ int      g_off[NN];        // CSR offsets; after scatter: END offsets
__device__ int      g_csr[EE];        // CSR: source row per incoming edge, bucketed by dst
__device__ float    g_dinv[NN];       // rsqrt(deg+1)
__device__ __half2  g_hs[NN * 32];    // transformed+scaled features, fp16 (128B/row)
__device__ float2   g_buf[NN * 32];   // layer-1 output (fp32, gemm2 input)
__device__ float    g_pool[GG * 64];  // pooled sums
__device__ int      g_gstart[GG + 1]; // graph segment starts
__device__ int      g_bsum[64];       // scan block sums
__device__ unsigned g_wfrag[2][2048]; // preformatted W fragments (half2 words) for both layers

// ---------------- init: zero counters/pool, graph bounds, W fragment preformat ----------------
// W fragment word o (layer l): reg=o&1, lane=(o>>1)&31, nt=(o>>6)&7, ktp=o>>9
//   n = nt*8 + lane/4 ; k = ktp*16 + reg*8 + (lane&3)*2 ; word = half2(W[n][k], W[n][k+1])
__global__ void k_zero(const int* __restrict__ batch,
                       const float* __restrict__ W1, const float* __restrict__ W2) {
    int i = blockIdx.x * blockDim.x + threadIdx.x;
    if (i < NN) g_deg[i] = 0;
    if (i < GG * 64) g_pool[i] = 0.f;
    if (i < 4096) {
        int l = i >> 11;
        int o = i & 2047;
        const float* W = l ? W2 : W1;
        int reg = o & 1, lane = (o >> 1) & 31, nt = (o >> 6) & 7, ktp = o >> 9;
        int n = nt * 8 + (lane >> 2);
        int k = ktp * 16 + reg * 8 + (lane & 3) * 2;
        __half2 h = __floats2half2_rn(W[n * 64 + k], W[n * 64 + k + 1]);
        g_wfrag[l][o] = *(unsigned*)&h;
    }
    if (i <= NN) {
        int prev = (i == 0) ? -1 : batch[i - 1];
        int cur  = (i < NN) ? batch[i] : GG;
        for (int g = prev + 1; g <= cur && g <= GG; g++) g_gstart[g] = i;
    }
}

// ---------------- degree histogram (4 edges/thread, vectorized load) ----------------
__global__ void k_degree(const int* __restrict__ ei) {
    int e = blockIdx.x * blockDim.x + threadIdx.x;
    if (e >= EE / 4) return;
    int4 c = ((const int4*)(ei + EE))[e];
    atomicAdd(&g_deg[c.x], 1);
    atomicAdd(&g_deg[c.y], 1);
    atomicAdd(&g_deg[c.z], 1);
    atomicAdd(&g_deg[c.w], 1);
}

// ---------------- scan stage A ----------------
__global__ void k_scan_a() {
    __shared__ int sh[256];
    int t = threadIdx.x;
    int base = blockIdx.x * 2048 + t * 8;
    int vals[8];
    int ts = 0;
#pragma unroll
    for (int j = 0; j < 8; j++) {
        int idx = base + j;
        vals[j] = (idx < NN) ? g_deg[idx] : 0;
        if (idx < NN) g_dinv[idx] = rsqrtf((float)(vals[j] + 1));
        ts += vals[j];
    }
    sh[t] = ts;
    __syncthreads();
#pragma unroll
    for (int d = 1; d < 256; d <<= 1) {
        int v = (t >= d) ? sh[t - d] : 0;
        __syncthreads();
        sh[t] += v;
        __syncthreads();
    }
    int excl = sh[t] - ts;
    int run = 0;
#pragma unroll
    for (int j = 0; j < 8; j++) {
        int idx = base + j;
        if (idx < NN) g_off[idx] = excl + run;
        run += vals[j];
    }
    if (t == 255) g_bsum[blockIdx.x] = sh[255];
}

// ---------------- scan stage C ----------------
__global__ void k_scan_c() {
    __shared__ int sv[64];
    __shared__ int pre;
    int t = threadIdx.x;
    int c = blockIdx.x >> 3;
    if (t < 64) sv[t] = (t < c) ? g_bsum[t] : 0;
    __syncthreads();
    if (t < 32) {
        int v = sv[t] + sv[t + 32];
#pragma unroll
        for (int d = 16; d > 0; d >>= 1) v += __shfl_down_sync(0xFFFFFFFFu, v, d);
        if (t == 0) pre = v;
    }
    __syncthreads();
    int i = blockIdx.x * 256 + t;
    if (i < NN) g_off[i] += pre;
}

// ---------------- CSR scatter (4 edges/thread) ----------------
__global__ void k_scatter(const int* __restrict__ ei) {
    int e = blockIdx.x * blockDim.x + threadIdx.x;
    if (e >= EE / 4) return;
    int4 r = ((const int4*)ei)[e];
    int4 c = ((const int4*)(ei + EE))[e];
    g_csr[atomicAdd(&g_off[c.x], 1)] = r.x;
    g_csr[atomicAdd(&g_off[c.y], 1)] = r.y;
    g_csr[atomicAdd(&g_off[c.z], 1)] = r.z;
    g_csr[atomicAdd(&g_off[c.w], 1)] = r.w;
}

// ---------------- GEMM via mma.sync m16n8k16 fp16 (fp32 accum) ----------------
// hs[v,:] = fp16( (X[v,:] @ W^T) * dinv[v] )
// Block: 128 thr / 4 warps / 64 rows. Warp w does rows [base+16w, base+16w+16).
__global__ void __launch_bounds__(128) k_gemm_mma(
    const float4* __restrict__ X4, const unsigned* __restrict__ wfrag,
    __half2* __restrict__ O) {
    __shared__ unsigned sA[4][4][32][4];   // [warp][ktp][lane][reg]  8KB
    __shared__ unsigned sB[2048];          // [ktp][nt][lane][reg]    8KB
    int tid = threadIdx.x;
    int base = blockIdx.x * 64;

    // stage B: coalesced copy of preformatted fragments
#pragma unroll
    for (int i = tid; i < 512; i += 128)
        ((uint4*)sB)[i] = ((const uint4*)wfrag)[i];

    // stage A: X rows -> fp16 fragments
    //   reg = (rr>=8) + 2*(jj>=2) ; lanes (rr&7)*4 + {2jj&3, 2jj&3+1}
    for (int i = tid; i < 1024; i += 128) {
        int r = i >> 4, j = i & 15;
        int R = base + r;
        float4 v = make_float4(0.f, 0.f, 0.f, 0.f);
        if (R < NN) v = X4[(size_t)R * 16 + j];
        int w = r >> 4, rr = r & 15;
        int ktp = j >> 2, jj = j & 3;
        int reg = ((rr >> 3) & 1) | ((jj >> 1) << 1);
        int t0 = (2 * jj) & 3;
        int lb = (rr & 7) * 4;
        __half2 h0 = __floats2half2_rn(v.x, v.y);
        __half2 h1 = __floats2half2_rn(v.z, v.w);
        sA[w][ktp][lb + t0][reg]     = *(unsigned*)&h0;
        sA[w][ktp][lb + t0 + 1][reg] = *(unsigned*)&h1;
    }
    __syncthreads();

    int lane = tid & 31;
    int w = tid >> 5;
    float d[8][4];
#pragma unroll
    for (int nt = 0; nt < 8; nt++)
#pragma unroll
        for (int j = 0; j < 4; j++) d[nt][j] = 0.f;

#pragma unroll
    for (int ktp = 0; ktp < 4; ktp++) {
        uint4 a = *(const uint4*)&sA[w][ktp][lane][0];  // LDS.128
#pragma unroll
        for (int nt = 0; nt < 8; nt++) {
            uint2 b = *(const uint2*)&sB[(((ktp << 3) + nt) << 6) + (lane << 1)];  // LDS.64
            asm volatile(
                "mma.sync.aligned.m16n8k16.row.col.f32.f16.f16.f32 "
                "{%0,%1,%2,%3}, {%4,%5,%6,%7}, {%8,%9}, {%0,%1,%2,%3};"
                : "+f"(d[nt][0]), "+f"(d[nt][1]), "+f"(d[nt][2]), "+f"(d[nt][3])
                : "r"(a.x), "r"(a.y), "r"(a.z), "r"(a.w), "r"(b.x), "r"(b.y));
        }
    }

    // epilogue: c0,c1 -> (row g, cols 2t..2t+1); c2,c3 -> (row g+8)
    int g = lane >> 2, t4 = lane & 3;
    int row0 = base + w * 16 + g;
    int row1 = row0 + 8;
    bool v0 = row0 < NN, v1 = row1 < NN;
    float dv0 = v0 ? g_dinv[row0] : 0.f;
    float dv1 = v1 ? g_dinv[row1] : 0.f;
#pragma unroll
    for (int nt = 0; nt < 8; nt++) {
        int cp = nt * 4 + t4;  // half2 column index
        if (v0) O[(size_t)row0 * 32 + cp] = __floats2half2_rn(d[nt][0] * dv0, d[nt][1] * dv0);
        if (v1) O[(size_t)row1 * 32 + cp] = __floats2half2_rn(d[nt][2] * dv1, d[nt][3] * dv1);
    }
}

// ---------------- aggregation + bias + BN + ReLU; optional fused pooling ----------------
template <bool POOL, int NODES_PER_BLK>
__global__ void k_agg(const __half2* __restrict__ hs, float2* __restrict__ out,
                      const int* __restrict__ batch,
                      const float* __restrict__ bias,
                      const float* __restrict__ bng, const float* __restrict__ bnb,
                      const float* __restrict__ bnm, const float* __restrict__ bnv) {
    __shared__ float sp[2][64];
    int t = threadIdx.x;
    int w0 = blockIdx.x * NODES_PER_BLK;
    int gid0 = 0, gidL = 0;
    if (POOL) {
        if (t < 128) sp[t >> 6][t & 63] = 0.f;
        gid0 = batch[w0];
        int wl = w0 + NODES_PER_BLK - 1;
        gidL = batch[wl < NN ? wl : NN - 1];
        __syncthreads();
    }
    int w = w0 + (t >> 5);
    int l = t & 31;
    float2 acc = make_float2(0.f, 0.f);
    if (w < NN) {
        float2 f = __half22float2(hs[w * 32 + l]);  // self loop
        acc = f;
        int e = g_off[w];
        int cnt = g_deg[w];
        int s = e - cnt;
        int i = 0;
        for (; i + 4 <= cnt; i += 4) {
            int r0 = g_csr[s + i + 0];
            int r1 = g_csr[s + i + 1];
            int r2 = g_csr[s + i + 2];
            int r3 = g_csr[s + i + 3];
            float2 a0 = __half22float2(hs[r0 * 32 + l]);
            float2 a1 = __half22float2(hs[r1 * 32 + l]);
            float2 a2 = __half22float2(hs[r2 * 32 + l]);
            float2 a3 = __half22float2(hs[r3 * 32 + l]);
            acc.x += (a0.x + a1.x) + (a2.x + a3.x);
            acc.y += (a0.y + a1.y) + (a2.y + a3.y);
        }
        for (; i < cnt; i++) {
            float2 a = __half22float2(hs[g_csr[s + i] * 32 + l]);
            acc.x += a.x;
            acc.y += a.y;
        }
        float dv = g_dinv[w];
        int c = 2 * l;
        float px = fmaf(acc.x, dv, bias[c]);
        float py = fmaf(acc.y, dv, bias[c + 1]);
        float sx = bng[c] * rsqrtf(bnv[c] + BN_EPS);
        float sy = bng[c + 1] * rsqrtf(bnv[c + 1] + BN_EPS);
        acc.x = fmaxf(0.f, fmaf(px - bnm[c], sx, bnb[c]));
        acc.y = fmaxf(0.f, fmaf(py - bnm[c + 1], sy, bnb[c + 1]));
        if (!POOL) {
            out[w * 32 + l] = acc;
        } else {
            int gid = batch[w];
            int slot = gid - gid0;
            int c2 = 2 * l;
            if (slot < 2) {
                atomicAdd(&sp[slot][c2], acc.x);
                atomicAdd(&sp[slot][c2 + 1], acc.y);
            } else {
                atomicAdd(&g_pool[gid * 64 + c2], acc.x);
                atomicAdd(&g_pool[gid * 64 + c2 + 1], acc.y);
            }
        }
    }
    if (POOL) {
        __syncthreads();
        if (t < 128) {
            int s = t >> 6, ch = t & 63;
            int gg = gid0 + s;
            if (gg <= gidL && gg < GG) atomicAdd(&g_pool[gg * 64 + ch], sp[s][ch]);
        }
    }
}

// ---------------- MLP head ----------------
__global__ void k_head(const float* __restrict__ l1W, const float* __restrict__ l1b,
                       const float* __restrict__ l2W, const float* __restrict__ l2b,
                       float* __restrict__ out) {
    __shared__ float sW1[32 * 64];
    __shared__ float sW2[32];
    __shared__ float sB1[32];
    int t = threadIdx.x;  // 64 threads
    for (int i = t; i < 2048; i += 64) sW1[i] = l1W[i];
    if (t < 32) { sW2[t] = l2W[t]; sB1[t] = l1b[t]; }
    __syncthreads();
    if (t >= GG) return;
    int g = t;
    int cnt = g_gstart[g + 1] - g_gstart[g];
    float inv = 1.f / fmaxf((float)cnt, 1.f);
    float p[64];
#pragma unroll
    for (int k = 0; k < 64; k++) p[k] = g_pool[g * 64 + k] * inv;
    float o = l2b[0];
#pragma unroll 4
    for (int j = 0; j < 32; j++) {
        float hsum = sB1[j];
#pragma unroll
        for (int k = 0; k < 64; k++) hsum = fmaf(p[k], sW1[j * 64 + k], hsum);
        o = fmaf(fmaxf(hsum, 0.f), sW2[j], o);
    }
    out[g] = o;
}

// ---------------- launch ----------------
extern "C" void kernel_launch(void* const* d_in, const int* in_sizes, int n_in,
                              void* d_out, int out_size) {
    const float* x      = (const float*)d_in[0];
    const int*   ei     = (const int*)d_in[1];
    const int*   batch  = (const int*)d_in[2];
    const float* W1     = (const float*)d_in[3];
    const float* b1     = (const float*)d_in[4];
    const float* W2     = (const float*)d_in[5];
    const float* b2     = (const float*)d_in[6];
    const float* bn1g   = (const float*)d_in[7];
    const float* bn1b   = (const float*)d_in[8];
    const float* bn1m   = (const float*)d_in[9];
    const float* bn1v   = (const float*)d_in[10];
    const float* bn2g   = (const float*)d_in[11];
    const float* bn2b   = (const float*)d_in[12];
    const float* bn2m   = (const float*)d_in[13];
    const float* bn2v   = (const float*)d_in[14];
    const float* l1W    = (const float*)d_in[15];
    const float* l1b    = (const float*)d_in[16];
    const float* l2W    = (const float*)d_in[17];
    const float* l2b    = (const float*)d_in[18];
    float* out = (float*)d_out;

    __half2* hs;
    float2* buf;
    unsigned* wfrag;
    cudaGetSymbolAddress((void**)&hs, g_hs);
    cudaGetSymbolAddress((void**)&buf, g_buf);
    cudaGetSymbolAddress((void**)&wfrag, g_wfrag);

    const int TB = 256;
    int nb_e4 = (EE / 4 + TB - 1) / TB;
    int nb_scan = (NN + 2047) / 2048;   // 49
    int nb_gemm = (NN + 63) / 64;       // 1563

    k_zero<<<(NN + 1 + TB - 1) / TB, TB>>>(batch, W1, W2);          // 0
    k_degree<<<nb_e4, TB>>>(ei);                                     // 1
    k_scan_a<<<nb_scan, 256>>>();                                    // 2
    k_gemm_mma<<<nb_gemm, 128>>>((const float4*)x, wfrag, hs);       // 3  <- ncu capture
    k_scan_c<<<(NN + 255) / 256, 256>>>();                           // 4
    k_scatter<<<nb_e4, TB>>>(ei);                                    // 5

    // layer 1: agg -> fp32 buf
    k_agg<false, 8><<<(NN + 7) / 8, 256>>>(hs, buf, batch, b1, bn1g, bn1b, bn1m, bn1v);      // 6
    // layer 2: transform
    k_gemm_mma<<<nb_gemm, 128>>>((const float4*)buf, wfrag + 2048, hs);                      // 7
    // layer 2: agg + fused pooling
    k_agg<true, 16><<<NN / 16, 512>>>(hs, nullptr, batch, b2, bn2g, bn2b, bn2m, bn2v);       // 8

    k_head<<<1, 64>>>(l1W, l1b, l2W, l2b, out);                      // 9
}